// round 17
// baseline (speedup 1.0000x reference)
#include <cuda_runtime.h>
#include <cuda_fp16.h>
#include <cstdint>
#include <math.h>

#define B_   16
#define S_   2048
#define E_   256
#define L_   2
#define NQ_  8
#define FFN_ 512
#define C_   2
#define M_   (B_*S_)   // 32768 rows

// ---------------- scratch (__device__ globals; no allocations) ---------------
__device__ __align__(128) __half g_wh[4*256*512];         // Wt[n][k] fp16
__device__ float g_pp[256*E_];                            // pool partials

// ---------------- smem layout (bytes) ----------------------------------------
#define STAGE   24576   // A 8192 + W 16384 per stage; 2 stages
#define W_O     8192
#define XRES_O  49152   // [128][256] fp16 residual x, 65536 B
#define W1S_O   114688  // [8][512] float ([n][f]), current layer, 16384 B
#define B1S_O   131072  // [512] float, 2048 B
#define QSH_O   133120  // [128][8] float, 4096 B
#define RED_O   137216  // [128][4] float2, 4096 B
#define MR_O    141312  // [128] float2, 1024 B
#define PPS_O   142336  // [2][256] float, 2048 B
#define SME_T   144384

// ---------------- PTX helpers ------------------------------------------------
__device__ __forceinline__ uint32_t s2u(const void* p) {
    uint32_t a;
    asm("{ .reg .u64 t; cvta.to.shared.u64 t, %1; cvt.u32.u64 %0, t; }"
        : "=r"(a) : "l"(p));
    return a;
}
__device__ __forceinline__ void cp16(uint32_t dst, const void* src) {
    asm volatile("cp.async.cg.shared.global [%0], [%1], 16;" :: "r"(dst), "l"(src));
}
__device__ __forceinline__ void cp_commit() {
    asm volatile("cp.async.commit_group;" ::: "memory");
}
__device__ __forceinline__ void cp_wait0() {
    asm volatile("cp.async.wait_group 0;" ::: "memory");
}
__device__ __forceinline__ void ldm_x4(uint32_t& r0, uint32_t& r1, uint32_t& r2,
                                       uint32_t& r3, uint32_t addr) {
    asm volatile("ldmatrix.sync.aligned.m8n8.x4.shared.b16 {%0,%1,%2,%3}, [%4];"
                 : "=r"(r0), "=r"(r1), "=r"(r2), "=r"(r3) : "r"(addr));
}
__device__ __forceinline__ void mma16816(float* c, uint32_t a0, uint32_t a1,
                                         uint32_t a2, uint32_t a3,
                                         uint32_t b0, uint32_t b1) {
    asm volatile(
        "mma.sync.aligned.m16n8k16.row.col.f32.f16.f16.f32 "
        "{%0,%1,%2,%3}, {%4,%5,%6,%7}, {%8,%9}, {%0,%1,%2,%3};"
        : "+f"(c[0]), "+f"(c[1]), "+f"(c[2]), "+f"(c[3])
        : "r"(a0), "r"(a1), "r"(a2), "r"(a3), "r"(b0), "r"(b1));
}

// ---------------- weight convert + transpose (fp16) --------------------------
__global__ void k_convw(const float* __restrict__ cw, const float* __restrict__ l2w) {
    int slot = blockIdx.y;
    int n    = blockIdx.x;
    int K    = (slot < 2) ? 256 : 512;
    const float* src = (slot < 2) ? (cw + (size_t)slot * E_ * E_)
                                  : (l2w + (size_t)(slot - 2) * FFN_ * E_);
    for (int k = threadIdx.x; k < K; k += 256) {
        float w = src[(size_t)k * E_ + n];
        g_wh[(size_t)slot * 131072 + (size_t)n * K + k] = __float2half_rn(w);
    }
}

// ---------------- GEMM phase: BM=128, BN=256, BK=32, 256 thr -----------------
// 8 warps (2M x 4N), warp tile 64x64. A chunk computed in-CTA each chunk:
//   SRC 0: a = cos(xres + theta[k&63])   (attn)
//   SRC 1: a = relu(q @ W1 + b1) fp16    (ffn)
// W loaded via cp.async (only global traffic). 64B rows, XOR-4 swizzle,
// 2-stage pipeline, 1 barrier/chunk.
template <int K, int SRC>
__device__ __forceinline__ void run_gemm(
    float (&acc)[4][8][4], char* smem, uint32_t sb,
    const float* __restrict__ th, const __half* __restrict__ W,
    const float* qsh, const float* w1s, const float* b1s) {
    constexpr int CH = K >> 5;
    int tid = threadIdx.x, lane = tid & 31, wid = tid >> 5;
    int wm = wid >> 2, wn = wid & 3;
    int part = tid & 3, rb = tid >> 2;                    // rb 0..63

    auto load_stage = [&](int st, int ch) {
        uint32_t dst = sb + st * STAGE;
        int kk = ch << 5;
#pragma unroll
        for (int i = 0; i < 4; i++) {
            int r = rb + i * 64;
            uint32_t sw = (uint32_t)(part ^ ((r >> 1) & 3)) << 4;
            cp16(dst + W_O + r * 64 + sw, W + (size_t)r * K + kk + part * 8);
        }
        cp_commit();
    };

    auto comp_src = [&](int st, int ch) {
        char* dst = smem + st * STAGE;
        int r = tid >> 1, half = tid & 1;                 // r 0..127
        int k0 = (ch << 5) + half * 16;
        __half2 hp[8];
        if constexpr (SRC == 0) {
            const __half2* xr = (const __half2*)(smem + XRES_O + r * 512
                                                 + (size_t)((k0 & 255) * 2));
#pragma unroll
            for (int j = 0; j < 8; j++) {
                float2 xv = __half22float2(xr[j]);
                int k = k0 + j * 2;
                hp[j] = __halves2half2(
                    __float2half_rn(__cosf(xv.x + th[k & 63])),
                    __float2half_rn(__cosf(xv.y + th[(k + 1) & 63])));
            }
        } else {
            float qr[8];
#pragma unroll
            for (int n = 0; n < 8; n++) qr[n] = qsh[r * 8 + n];
#pragma unroll
            for (int j = 0; j < 8; j++) {
                float hv[2];
#pragma unroll
                for (int u = 0; u < 2; u++) {
                    int f = k0 + j * 2 + u;
                    float h = b1s[f];
#pragma unroll
                    for (int n = 0; n < 8; n++) h += qr[n] * w1s[n * 512 + f];
                    hv[u] = fmaxf(h, 0.f);
                }
                hp[j] = __halves2half2(__float2half_rn(hv[0]),
                                       __float2half_rn(hv[1]));
            }
        }
        uint32_t swz = (uint32_t)((r >> 1) & 3);
        uint32_t o0 = (uint32_t)r * 64 + (((uint32_t)(half * 2)     ^ swz) << 4);
        uint32_t o1 = (uint32_t)r * 64 + (((uint32_t)(half * 2 + 1) ^ swz) << 4);
        *(uint4*)(dst + o0) = *(uint4*)&hp[0];
        *(uint4*)(dst + o1) = *(uint4*)&hp[4];
    };

    load_stage(0, 0);
    comp_src(0, 0);

    uint32_t rowA = wm * 64 + (lane & 15);
    uint32_t rxA  = (rowA >> 1) & 3;
    uint32_t cA   = (uint32_t)lane >> 4;
    uint32_t rowB = wn * 64 + ((lane >> 4) & 1) * 8 + (lane & 7);
    uint32_t rxB  = (rowB >> 1) & 3;
    uint32_t cB   = ((uint32_t)lane >> 3) & 1;

    for (int cc = 0; cc < CH; cc++) {
        cp_wait0();
        __syncthreads();
        if (cc + 1 < CH) {
            load_stage((cc + 1) & 1, cc + 1);
            comp_src((cc + 1) & 1, cc + 1);
        }
        uint32_t stg = sb + (cc & 1) * STAGE;
        uint32_t aB  = stg + rowA * 64;
        uint32_t bB  = stg + W_O + rowB * 64;

#pragma unroll
        for (int kb = 0; kb < 2; kb++) {
            uint32_t colA = (((uint32_t)(kb * 2) + cA) ^ rxA) << 4;
            uint32_t colB = (((uint32_t)(kb * 2) + cB) ^ rxB) << 4;
            uint32_t b[16];
#pragma unroll
            for (int n2 = 0; n2 < 4; n2++)
                ldm_x4(b[n2*4], b[n2*4+1], b[n2*4+2], b[n2*4+3],
                       bB + n2 * 1024 + colB);
            uint32_t a0[4], a1[4], a2[4], a3[4];
#pragma unroll
            for (int mi = 0; mi < 4; mi++)
                ldm_x4(a0[mi], a1[mi], a2[mi], a3[mi], aB + mi * 1024 + colA);
#pragma unroll
            for (int mi = 0; mi < 4; mi++)
#pragma unroll
                for (int n2 = 0; n2 < 4; n2++) {
                    mma16816(acc[mi][n2*2],   a0[mi], a1[mi], a2[mi], a3[mi],
                             b[n2*4],   b[n2*4+1]);
                    mma16816(acc[mi][n2*2+1], a0[mi], a1[mi], a2[mi], a3[mi],
                             b[n2*4+2], b[n2*4+3]);
                }
        }
    }
    __syncthreads();   // stage-buffer reads done before reuse
}

// ---------------- epilogue: residual(smem) + LN (+ producer) -----------------
// PROD 0: write xres + q->qsh.  PROD 1: write xres.  PROD 2: pool partials.
template <int PROD>
__device__ __forceinline__ void epilogue(
    float (&acc)[4][8][4], char* smem,
    const float* __restrict__ bias,
    const float* __restrict__ lnG, const float* __restrict__ lnB,
    const float* __restrict__ fTh) {
    float2*  red = (float2*)(smem + RED_O);
    float2*  mr  = (float2*)(smem + MR_O);
    float*   qsh = (float*)(smem + QSH_O);
    float*   pps = (float*)(smem + PPS_O);
    __half2* xr  = (__half2*)(smem + XRES_O);
    int tid = threadIdx.x, lane = tid & 31, wid = tid >> 5;
    int wm = wid >> 2, wn = wid & 3;
    int mcol = wn * 64 + (lane & 3) * 2;
    int r0l  = lane >> 2;                                 // 0..7

#pragma unroll
    for (int mi = 0; mi < 4; mi++) {
        float s0 = 0, q0 = 0, s1 = 0, q1 = 0;
        int rl = wm * 64 + r0l + mi * 16;
#pragma unroll
        for (int ni = 0; ni < 8; ni++) {
            int col = mcol + ni * 8;
            float2 x0 = __half22float2(xr[rl * 128 + (col >> 1)]);
            float2 x1 = __half22float2(xr[(rl + 8) * 128 + (col >> 1)]);
            float bcx = bias[col], bcy = bias[col + 1];
            float v0 = acc[mi][ni][0] + bcx + x0.x;
            float v1 = acc[mi][ni][1] + bcy + x0.y;
            float v2 = acc[mi][ni][2] + bcx + x1.x;
            float v3 = acc[mi][ni][3] + bcy + x1.y;
            acc[mi][ni][0] = v0; acc[mi][ni][1] = v1;
            acc[mi][ni][2] = v2; acc[mi][ni][3] = v3;
            s0 += v0 + v1; q0 += v0 * v0 + v1 * v1;
            s1 += v2 + v3; q1 += v2 * v2 + v3 * v3;
        }
#pragma unroll
        for (int o = 1; o <= 2; o <<= 1) {
            s0 += __shfl_xor_sync(0xffffffffu, s0, o);
            q0 += __shfl_xor_sync(0xffffffffu, q0, o);
            s1 += __shfl_xor_sync(0xffffffffu, s1, o);
            q1 += __shfl_xor_sync(0xffffffffu, q1, o);
        }
        if ((lane & 3) == 0) {
            red[rl * 4 + wn] = make_float2(s0, q0);
            red[(rl + 8) * 4 + wn] = make_float2(s1, q1);
        }
    }
    __syncthreads();
    if (tid < 128) {
        float s = 0, q = 0;
#pragma unroll
        for (int j = 0; j < 4; j++) { float2 t = red[tid * 4 + j]; s += t.x; q += t.y; }
        float mean = s * (1.0f / E_);
        float var  = q * (1.0f / E_) - mean * mean;
        mr[tid] = make_float2(mean, rsqrtf(var + 1e-5f));
    }
    __syncthreads();

    float cf0 = 0.f, cf1 = 0.f;
    if constexpr (PROD == 0) {
        int c = (lane & 3) * 2;
        cf0 = __cosf(fTh[c]); cf1 = __cosf(fTh[c + 1]);
    }
    float ps[8][2];
    if constexpr (PROD == 2) {
#pragma unroll
        for (int ni = 0; ni < 8; ni++) { ps[ni][0] = 0.f; ps[ni][1] = 0.f; }
    }

#pragma unroll
    for (int mi = 0; mi < 4; mi++) {
        int rl = wm * 64 + r0l + mi * 16;
        float2 m0 = mr[rl], m1 = mr[rl + 8];
#pragma unroll
        for (int ni = 0; ni < 8; ni++) {
            int col = mcol + ni * 8;
            float gx = lnG[col], gy = lnG[col + 1];
            float bx = lnB[col], by = lnB[col + 1];
            float o0 = (acc[mi][ni][0] - m0.x) * m0.y * gx + bx;
            float o1 = (acc[mi][ni][1] - m0.x) * m0.y * gy + by;
            float o2 = (acc[mi][ni][2] - m1.x) * m1.y * gx + bx;
            float o3 = (acc[mi][ni][3] - m1.x) * m1.y * gy + by;
            if constexpr (PROD != 2) {
                xr[rl * 128 + (col >> 1)] =
                    __halves2half2(__float2half_rn(o0), __float2half_rn(o1));
                xr[(rl + 8) * 128 + (col >> 1)] =
                    __halves2half2(__float2half_rn(o2), __float2half_rn(o3));
            }
            if constexpr (PROD == 0) {
                if (wn == 0 && ni == 0) {
                    int c = (lane & 3) * 2;
                    qsh[rl * 8 + c]           = __cosf(o0) * cf0;
                    qsh[rl * 8 + c + 1]       = __cosf(o1) * cf1;
                    qsh[(rl + 8) * 8 + c]     = __cosf(o2) * cf0;
                    qsh[(rl + 8) * 8 + c + 1] = __cosf(o3) * cf1;
                }
            }
            if constexpr (PROD == 2) {
                ps[ni][0] += o0 + o2;
                ps[ni][1] += o1 + o3;
            }
        }
    }

    if constexpr (PROD == 2) {
        // intra-warp: sum over r0l (lanes differing in bits 2..4) -> 64-row sums
#pragma unroll
        for (int ni = 0; ni < 8; ni++)
#pragma unroll
            for (int o = 4; o <= 16; o <<= 1) {
                ps[ni][0] += __shfl_xor_sync(0xffffffffu, ps[ni][0], o);
                ps[ni][1] += __shfl_xor_sync(0xffffffffu, ps[ni][1], o);
            }
        if (lane < 4) {
#pragma unroll
            for (int ni = 0; ni < 8; ni++) {
                pps[wm * 256 + mcol + ni * 8]     = ps[ni][0];
                pps[wm * 256 + mcol + ni * 8 + 1] = ps[ni][1];
            }
        }
        __syncthreads();
        if (tid < 256)
            g_pp[blockIdx.x * 256 + tid] = pps[tid] + pps[256 + tid];
    }
}

// ---------------- whole network, activations CTA-resident in smem ------------
__global__ void __launch_bounds__(256, 1)
k_net(const int* __restrict__ tokens, const float* __restrict__ emb,
      const float* __restrict__ attn_theta,
      const float* __restrict__ combine_b,
      const float* __restrict__ ffn_theta,
      const float* __restrict__ lin1_w, const float* __restrict__ lin1_b,
      const float* __restrict__ lin2_b,
      const float* __restrict__ ln1_g, const float* __restrict__ ln1_b,
      const float* __restrict__ ln2_g, const float* __restrict__ ln2_b) {
    extern __shared__ __align__(16) char smem[];
    uint32_t sb = s2u(smem);
    int tid = threadIdx.x;
    size_t bm = (size_t)blockIdx.x * 128;

    float* w1s = (float*)(smem + W1S_O);
    float* b1s = (float*)(smem + B1S_O);
    float* qsh = (float*)(smem + QSH_O);

    // ---- embed prologue: rows bm..bm+127 -> xres (fp16, smem) ----
    {
        __half2* xr = (__half2*)(smem + XRES_O);
#pragma unroll
        for (int i = 0; i < 32; i++) {
            int idx = tid + i * 256;
            int r   = idx >> 6;                 // 0..127
            int c   = (idx & 63) * 4;
            size_t row = bm + r;
            int s = (int)(row & (S_ - 1));
            int t = tokens[row];
            float4 ev = *(const float4*)(emb + (size_t)t * E_ + c);
            float xs[4];
#pragma unroll
            for (int j = 0; j < 4; j++) {
                int e = c + j;
                float freq = __expf(-(float)(e & ~1) * (9.210340371976184f / (float)E_));
                float ang  = (float)s * freq;
                float pe   = (e & 1) ? __cosf(ang) : __sinf(ang);
                xs[j] = ((const float*)&ev)[j] + pe;
            }
            xr[r * 128 + (c >> 1)] =
                __halves2half2(__float2half_rn(xs[0]), __float2half_rn(xs[1]));
            xr[r * 128 + (c >> 1) + 1] =
                __halves2half2(__float2half_rn(xs[2]), __float2half_rn(xs[3]));
        }
    }
    __syncthreads();

    float acc[4][8][4];
#pragma unroll
    for (int l = 0; l < L_; l++) {
        // stage W1/b1 (first used in ffn comp_src, after multiple barriers)
#pragma unroll
        for (int i = 0; i < 16; i++)
            w1s[tid + i * 256] = lin1_w[(size_t)l * NQ_ * FFN_ + tid + i * 256];
#pragma unroll
        for (int i = 0; i < 2; i++)
            b1s[tid + i * 256] = lin1_b[l * FFN_ + tid + i * 256];

        // attn GEMM (K=256, A = cos(xres+theta) computed in-CTA)
#pragma unroll
        for (int i = 0; i < 4; i++)
#pragma unroll
            for (int j = 0; j < 8; j++)
#pragma unroll
                for (int c = 0; c < 4; c++) acc[i][j][c] = 0.f;
        run_gemm<256, 0>(acc, smem, sb, attn_theta + l * 64,
                         g_wh + (size_t)l * 131072, nullptr, nullptr, nullptr);
        epilogue<0>(acc, smem, combine_b + l * E_,
                    ln1_g + l * E_, ln1_b + l * E_, ffn_theta + l * NQ_);
        __syncthreads();   // qsh + xres ready

        // ffn GEMM (K=512, A = relu(q@W1+b1) computed in-CTA)
#pragma unroll
        for (int i = 0; i < 4; i++)
#pragma unroll
            for (int j = 0; j < 8; j++)
#pragma unroll
                for (int c = 0; c < 4; c++) acc[i][j][c] = 0.f;
        run_gemm<512, 1>(acc, smem, sb, nullptr,
                         g_wh + (size_t)(2 + l) * 131072, qsh, w1s, b1s);
        if (l == 0) {
            epilogue<1>(acc, smem, lin2_b, ln2_g, ln2_b, nullptr);
            __syncthreads();   // xres ready for layer-1 comp_src
        } else {
            epilogue<2>(acc, smem, lin2_b + E_, ln2_g + E_, ln2_b + E_, nullptr);
        }
    }
}

// ---------------- classifier -------------------------------------------------
__global__ void k_cls(const float* __restrict__ w, const float* __restrict__ cb,
                      float* __restrict__ out) {
    __shared__ float sh[16];
    int b = blockIdx.x, e = threadIdx.x;
    float p = 0.f;
#pragma unroll
    for (int j = 0; j < 16; j++) p += g_pp[(b * 16 + j) * E_ + e];
    p *= (1.0f / (float)S_);
    float s0 = p * w[e * 2], s1 = p * w[e * 2 + 1];
    for (int o = 16; o > 0; o >>= 1) {
        s0 += __shfl_xor_sync(0xffffffffu, s0, o);
        s1 += __shfl_xor_sync(0xffffffffu, s1, o);
    }
    int wi = e >> 5;
    if ((e & 31) == 0) { sh[wi * 2] = s0; sh[wi * 2 + 1] = s1; }
    __syncthreads();
    if (e == 0) {
        float t0 = 0, t1 = 0;
#pragma unroll
        for (int j = 0; j < 8; j++) { t0 += sh[j * 2]; t1 += sh[j * 2 + 1]; }
        out[b * 2]     = t0 + cb[0];
        out[b * 2 + 1] = t1 + cb[1];
    }
}

// ---------------- host launcher ----------------------------------------------
extern "C" void kernel_launch(void* const* d_in, const int* in_sizes, int n_in,
                              void* d_out, int out_size) {
    const int*   tokens     = (const int*)d_in[0];
    const float* embed      = (const float*)d_in[1];
    const float* attn_theta = (const float*)d_in[2];
    const float* combine_w  = (const float*)d_in[3];
    const float* combine_b  = (const float*)d_in[4];
    const float* ffn_theta  = (const float*)d_in[5];
    const float* lin1_w     = (const float*)d_in[6];
    const float* lin1_b     = (const float*)d_in[7];
    const float* lin2_w     = (const float*)d_in[8];
    const float* lin2_b     = (const float*)d_in[9];
    const float* ln1_g      = (const float*)d_in[10];
    const float* ln1_b      = (const float*)d_in[11];
    const float* ln2_g      = (const float*)d_in[12];
    const float* ln2_b      = (const float*)d_in[13];
    const float* cls_w      = (const float*)d_in[14];
    const float* cls_b      = (const float*)d_in[15];
    float* out = (float*)d_out;

    cudaFuncSetAttribute(k_net, cudaFuncAttributeMaxDynamicSharedMemorySize, SME_T);

    k_convw<<<dim3(256, 4), 256>>>(combine_w, lin2_w);
    k_net<<<M_ / 128, 256, SME_T>>>(tokens, embed, attn_theta, combine_b,
                                    ffn_theta, lin1_w, lin1_b, lin2_b,
                                    ln1_g, ln1_b, ln2_g, ln2_b);
    k_cls<<<B_, 256>>>(cls_w, cls_b, out);
}